// round 14
// baseline (speedup 1.0000x reference)
#include <cuda_runtime.h>

#define ND 128
#define HID 16
#define N_MAX 100000

typedef unsigned long long u64;

// Device-global scratch; statically zeroed; each run restores its own state
// so graph replays see identical initial conditions.
__device__ __align__(16) int   g_degi[N_MAX];    // reset by rcp_kernel
__device__ __align__(16) float g_invdeg[N_MAX];
__device__ __align__(16) float g_w[N_MAX];       // reset by node_kernel
__device__ __align__(16) float g_s[N_MAX];
__device__ float    g_acc;                       // reset by last node_kernel block
__device__ unsigned g_done;                      // wraps via atomicInc

#define FMA2(d, a, b) \
    asm("fma.rn.f32x2 %0, %1, %2, %3;" : "=l"(d) : "l"(a), "l"(b), "l"(d))
#define PACK2(d, s) \
    asm("mov.b64 %0, {%1, %1};" : "=l"(d) : "r"(__float_as_uint(s)))
#define UNPACK2(lo, hi, s) \
    asm("mov.b64 {%0, %1}, %2;" : "=r"(lo), "=r"(hi) : "l"(s))

__device__ __forceinline__ float ftanh(float v) {
    return 1.0f - __fdividef(2.0f, __expf(2.0f * v) + 1.0f);
}

// ---------------- stream B1: deg scatter (int RED.32) ----------------
#define DEG_TPB 256
#define DEG_EPT 8
__global__ void __launch_bounds__(DEG_TPB) deg_kernel(const int* __restrict__ esrc, int e) {
    long base = (long)(blockIdx.x * DEG_TPB + threadIdx.x) * DEG_EPT;
    if (base + DEG_EPT <= e) {
        int4 sa = *(const int4*)(esrc + base);
        int4 sb = *(const int4*)(esrc + base + 4);
        atomicAdd(&g_degi[sa.x], 1);
        atomicAdd(&g_degi[sa.y], 1);
        atomicAdd(&g_degi[sa.z], 1);
        atomicAdd(&g_degi[sa.w], 1);
        atomicAdd(&g_degi[sb.x], 1);
        atomicAdd(&g_degi[sb.y], 1);
        atomicAdd(&g_degi[sb.z], 1);
        atomicAdd(&g_degi[sb.w], 1);
    } else {
        for (long i = base; i < e; i++) atomicAdd(&g_degi[esrc[i]], 1);
    }
}

// ---------------- stream B2: invdeg = 1/deg, reset deg ----------------
__global__ void rcp_kernel(int n) {
    int i = blockIdx.x * blockDim.x + threadIdx.x;
    if (i < n) {
        int d = g_degi[i];
        g_invdeg[i] = __frcp_rn((float)d);  // inf for d==0, never read (src deg>=1)
        g_degi[i] = 0;                       // restore for next replay
    }
}

// ------- stream B3: w-scatter: w[dst] += invdeg[src] (gather + RED) -------
#define W_TPB 256
#define W_EPT 8
__global__ void __launch_bounds__(W_TPB) w_kernel(
    const int* __restrict__ src, const int* __restrict__ dst, int e)
{
    long base = (long)(blockIdx.x * W_TPB + threadIdx.x) * W_EPT;
    if (base + W_EPT <= e) {
        int4 sa = *(const int4*)(src + base);
        int4 sb = *(const int4*)(src + base + 4);
        int4 da = *(const int4*)(dst + base);
        int4 db = *(const int4*)(dst + base + 4);
        float w0 = __ldg(&g_invdeg[sa.x]), w1 = __ldg(&g_invdeg[sa.y]);
        float w2 = __ldg(&g_invdeg[sa.z]), w3 = __ldg(&g_invdeg[sa.w]);
        float w4 = __ldg(&g_invdeg[sb.x]), w5 = __ldg(&g_invdeg[sb.y]);
        float w6 = __ldg(&g_invdeg[sb.z]), w7 = __ldg(&g_invdeg[sb.w]);
        atomicAdd(&g_w[da.x], w0);
        atomicAdd(&g_w[da.y], w1);
        atomicAdd(&g_w[da.z], w2);
        atomicAdd(&g_w[da.w], w3);
        atomicAdd(&g_w[db.x], w4);
        atomicAdd(&g_w[db.y], w5);
        atomicAdd(&g_w[db.z], w6);
        atomicAdd(&g_w[db.w], w7);
    } else {
        for (long i = base; i < e; i++)
            atomicAdd(&g_w[dst[i]], __ldg(&g_invdeg[src[i]]));
    }
}

// ------- stream A: MLP -> s (R11 proven: NPT=2, pipelined smem staging) ----
#define MLP_TPB 128
#define MLP_NPT 2                 // 256 nodes per block
#define NB (MLP_TPB * MLP_NPT)    // 256
#define KT 8                      // 8 k-tiles of 16 floats (4 float4)

__global__ void __launch_bounds__(MLP_TPB) mlp_kernel(
    const float* __restrict__ x,
    const float* __restrict__ W1, const float* __restrict__ b1,
    const float* __restrict__ W2, const float* __restrict__ b2,
    const float* __restrict__ W3, const float* __restrict__ b3,
    const float* __restrict__ Wc,
    int n)
{
    __shared__ float4 sX[NB * 5];          // 256 rows x (4 float4 + 1 pad)
    __shared__ float4 sW1[ND * HID / 4];   // 8KB
    __shared__ float4 sW2[HID * HID / 4];
    __shared__ float4 sW3[HID * HID / 4];
    __shared__ u64 sb1[8], sb2[8], sb3[8];
    __shared__ float sWc[HID];

    int tid = threadIdx.x;
    for (int i = tid; i < ND * HID / 4; i += MLP_TPB) sW1[i] = ((const float4*)W1)[i];
    if (tid < HID * HID / 4) {
        sW2[tid] = ((const float4*)W2)[tid];
        sW3[tid] = ((const float4*)W3)[tid];
    }
    if (tid < 8) {
        sb1[tid] = ((const u64*)b1)[tid];
        sb2[tid] = ((const u64*)b2)[tid];
        sb3[tid] = ((const u64*)b3)[tid];
    }
    if (tid < HID) sWc[tid] = Wc[tid];

    int nodeBase = blockIdx.x * NB;
    int r0 = tid, r1 = tid + MLP_TPB;
    int myN0 = min(nodeBase + r0, n - 1);
    int myN1 = min(nodeBase + r1, n - 1);

    // cooperative-load coordinates (fixed across tiles): 8 float4 per thread
    int lr[8], lj[8];
    const float4* lg[8];
#pragma unroll
    for (int i = 0; i < 8; i++) {
        int lin = i * MLP_TPB + tid;
        lr[i] = lin >> 2;
        lj[i] = lin & 3;
        int gn = min(nodeBase + lr[i], n - 1);
        lg[i] = ((const float4*)(x + (size_t)gn * ND)) + lj[i];
    }

    u64 h0[8], h1v[8];

    // prologue: issue loads for tile 0
    float4 v[8];
#pragma unroll
    for (int i = 0; i < 8; i++) v[i] = lg[i][0];

    __syncthreads();  // weights + biases visible
#pragma unroll
    for (int q = 0; q < 8; q++) { h0[q] = sb1[q]; h1v[q] = sb1[q]; }

    // ---- layer 1 over 8 k-tiles of 16 floats, software-pipelined ----
#pragma unroll
    for (int kt = 0; kt < KT; kt++) {
        if (kt > 0) __syncthreads();
#pragma unroll
        for (int i = 0; i < 8; i++) sX[lr[i] * 5 + lj[i]] = v[i];
        __syncthreads();

        if (kt + 1 < KT) {
#pragma unroll
            for (int i = 0; i < 8; i++) v[i] = lg[i][(kt + 1) * 4];
        }

#pragma unroll
        for (int j = 0; j < 4; j++) {
            float4 xa = sX[r0 * 5 + j];
            float4 xb = sX[r1 * 5 + j];
            float xas[4] = {xa.x, xa.y, xa.z, xa.w};
            float xbs[4] = {xb.x, xb.y, xb.z, xb.w};
#pragma unroll
            for (int i = 0; i < 4; i++) {
                int k = kt * 16 + j * 4 + i;
                const ulonglong2* wr = (const ulonglong2*)(sW1 + k * 4);
                u64 xpa, xpb;
                PACK2(xpa, xas[i]);
                PACK2(xpb, xbs[i]);
#pragma unroll
                for (int q = 0; q < 4; q++) {
                    ulonglong2 ww = wr[q];
                    FMA2(h0[2 * q],      xpa, ww.x);
                    FMA2(h0[2 * q + 1],  xpa, ww.y);
                    FMA2(h1v[2 * q],     xpb, ww.x);
                    FMA2(h1v[2 * q + 1], xpb, ww.y);
                }
            }
        }
    }

    float t0[HID], t1[HID];
#pragma unroll
    for (int q = 0; q < 8; q++) {
        unsigned lo, hi;
        UNPACK2(lo, hi, h0[q]);
        t0[2 * q] = ftanh(__uint_as_float(lo));
        t0[2 * q + 1] = ftanh(__uint_as_float(hi));
        UNPACK2(lo, hi, h1v[q]);
        t1[2 * q] = ftanh(__uint_as_float(lo));
        t1[2 * q + 1] = ftanh(__uint_as_float(hi));
    }

    // ---- layer 2 ----
    u64 a0[8], a1[8];
#pragma unroll
    for (int q = 0; q < 8; q++) { a0[q] = sb2[q]; a1[q] = sb2[q]; }
#pragma unroll
    for (int i = 0; i < HID; i++) {
        const ulonglong2* wr = (const ulonglong2*)(sW2 + i * 4);
        u64 p0, p1;
        PACK2(p0, t0[i]);
        PACK2(p1, t1[i]);
#pragma unroll
        for (int q = 0; q < 4; q++) {
            ulonglong2 ww = wr[q];
            FMA2(a0[2 * q],     p0, ww.x);
            FMA2(a0[2 * q + 1], p0, ww.y);
            FMA2(a1[2 * q],     p1, ww.x);
            FMA2(a1[2 * q + 1], p1, ww.y);
        }
    }
#pragma unroll
    for (int q = 0; q < 8; q++) {
        unsigned lo, hi;
        UNPACK2(lo, hi, a0[q]);
        t0[2 * q] = ftanh(__uint_as_float(lo));
        t0[2 * q + 1] = ftanh(__uint_as_float(hi));
        UNPACK2(lo, hi, a1[q]);
        t1[2 * q] = ftanh(__uint_as_float(lo));
        t1[2 * q + 1] = ftanh(__uint_as_float(hi));
    }

    // ---- layer 3 ----
#pragma unroll
    for (int q = 0; q < 8; q++) { a0[q] = sb3[q]; a1[q] = sb3[q]; }
#pragma unroll
    for (int i = 0; i < HID; i++) {
        const ulonglong2* wr = (const ulonglong2*)(sW3 + i * 4);
        u64 p0, p1;
        PACK2(p0, t0[i]);
        PACK2(p1, t1[i]);
#pragma unroll
        for (int q = 0; q < 4; q++) {
            ulonglong2 ww = wr[q];
            FMA2(a0[2 * q],     p0, ww.x);
            FMA2(a0[2 * q + 1], p0, ww.y);
            FMA2(a1[2 * q],     p1, ww.x);
            FMA2(a1[2 * q + 1], p1, ww.y);
        }
    }

    // tanh + contract with Wc -> scalar per node
    float s0 = 0.f, s1 = 0.f;
#pragma unroll
    for (int q = 0; q < 8; q++) {
        unsigned lo, hi;
        UNPACK2(lo, hi, a0[q]);
        s0 += ftanh(__uint_as_float(lo)) * sWc[2 * q];
        s0 += ftanh(__uint_as_float(hi)) * sWc[2 * q + 1];
        UNPACK2(lo, hi, a1[q]);
        s1 += ftanh(__uint_as_float(lo)) * sWc[2 * q];
        s1 += ftanh(__uint_as_float(hi)) * sWc[2 * q + 1];
    }
    // clamped duplicate writes carry identical values -> benign
    g_s[myN0] = s0;
    g_s[myN1] = s1;
}

// ---- join: node pass: acc = sum_m s[m]*w[m]; sigmoid; reset state ----
#define N_TPB 256

__global__ void __launch_bounds__(N_TPB) node_kernel(
    const float* __restrict__ bc, float* __restrict__ out, int n, float inv_n)
{
    __shared__ float sRed[N_TPB / 32];
    int tid = threadIdx.x;
    int i = blockIdx.x * N_TPB + tid;
    float term = 0.f;

    if (i < n) {
        float w = g_w[i];
        if (w != 0.f) {
            term = g_s[i] * w;
            g_w[i] = 0.f;  // restore for next graph replay
        }
    }

    unsigned m = 0xffffffffu;
#pragma unroll
    for (int off = 16; off > 0; off >>= 1)
        term += __shfl_down_sync(m, term, off);
    if ((tid & 31) == 0) sRed[tid >> 5] = term;
    __syncthreads();

    if (tid == 0) {
        float v = 0.f;
#pragma unroll
        for (int wq = 0; wq < N_TPB / 32; wq++) v += sRed[wq];
        atomicAdd(&g_acc, v);
        __threadfence();
        unsigned ticket = atomicInc(&g_done, gridDim.x - 1);  // wraps to 0 on last
        if (ticket == gridDim.x - 1) {
            float z = g_acc * inv_n + bc[0];
            out[0] = 1.0f / (1.0f + __expf(-z));
            g_acc = 0.f;  // restore for next replay
        }
    }
}

extern "C" void kernel_launch(void* const* d_in, const int* in_sizes, int n_in,
                              void* d_out, int out_size) {
    const float* x    = (const float*)d_in[0];
    const int*   esrc = (const int*)  d_in[1];
    const int*   edst = (const int*)  d_in[2];
    const float* W1   = (const float*)d_in[3];
    const float* b1   = (const float*)d_in[4];
    const float* W2   = (const float*)d_in[5];
    const float* b2   = (const float*)d_in[6];
    const float* W3   = (const float*)d_in[7];
    const float* b3   = (const float*)d_in[8];
    const float* Wc   = (const float*)d_in[9];
    const float* bc   = (const float*)d_in[10];
    float* out = (float*)d_out;

    int n = in_sizes[0] / ND;
    int e = in_sizes[1];
    if (n > N_MAX) n = N_MAX;

    // One-time resources (created on the uncaptured correctness run; reused
    // under capture; identical work per call -> deterministic)
    static cudaStream_t s2 = 0;
    static cudaEvent_t evFork = 0, evJoin = 0;
    static int inited = 0;
    if (!inited) {
        cudaStreamCreateWithFlags(&s2, cudaStreamNonBlocking);
        cudaEventCreateWithFlags(&evFork, cudaEventDisableTiming);
        cudaEventCreateWithFlags(&evJoin, cudaEventDisableTiming);
        inited = 1;
    }

    // ---- fork: edge pipeline (deg -> rcp -> w) on s2, MLP on stream 0 ----
    cudaEventRecord(evFork, 0);
    cudaStreamWaitEvent(s2, evFork, 0);

    int nDeg = (e + DEG_TPB * DEG_EPT - 1) / (DEG_TPB * DEG_EPT);
    deg_kernel<<<nDeg, DEG_TPB, 0, s2>>>(esrc, e);
    rcp_kernel<<<(n + 255) / 256, 256, 0, s2>>>(n);
    int nW = (e + W_TPB * W_EPT - 1) / (W_TPB * W_EPT);
    w_kernel<<<nW, W_TPB, 0, s2>>>(esrc, edst, e);

    int nMlp = (n + NB - 1) / NB;
    mlp_kernel<<<nMlp, MLP_TPB>>>(x, W1, b1, W2, b2, W3, b3, Wc, n);

    // ---- join, then node contraction + output ----
    cudaEventRecord(evJoin, s2);
    cudaStreamWaitEvent(0, evJoin, 0);

    int nNode = (n + N_TPB - 1) / N_TPB;
    node_kernel<<<nNode, N_TPB>>>(bc, out, n, 1.0f / (float)n);
}

// round 16
// speedup vs baseline: 1.5400x; 1.5400x over previous
#include <cuda_runtime.h>
#include <cuda_bf16.h>
#include <cstdint>

#define ND 128
#define HID 16
#define N_MAX 100000

typedef unsigned long long u64;

// Device-global scratch; statically zeroed; each run restores its own state.
__device__ __align__(16) int g_udi[N_MAX];   // cnt*2^24 + sum(s*2^16); reset by node_kernel
__device__ __align__(16) int g_si[N_MAX];    // per-node fixed-point: 2^24 + round(s*2^16)
__device__ float    g_acc;                   // reset by last node_kernel block
__device__ unsigned g_done;                  // wraps via atomicInc

#define FMA2(d, a, b) \
    asm("fma.rn.f32x2 %0, %1, %2, %3;" : "=l"(d) : "l"(a), "l"(b), "l"(d))
#define PACK2(d, s) \
    asm("mov.b64 %0, {%1, %1};" : "=l"(d) : "r"(__float_as_uint(s)))

__device__ __forceinline__ float ftanh(float v) {
    return 1.0f - __fdividef(2.0f, __expf(2.0f * v) + 1.0f);
}

#define LDSM4(r, addr) \
    asm volatile("ldmatrix.sync.aligned.m8n8.x4.shared.b16 {%0,%1,%2,%3}, [%4];" \
        : "=r"((r)[0]), "=r"((r)[1]), "=r"((r)[2]), "=r"((r)[3]) : "r"(addr))
#define LDSM2(r, addr) \
    asm volatile("ldmatrix.sync.aligned.m8n8.x2.shared.b16 {%0,%1}, [%2];" \
        : "=r"((r)[0]), "=r"((r)[1]) : "r"(addr))
#define MMA16816(c, a, b) \
    asm volatile("mma.sync.aligned.m16n8k16.row.col.f32.bf16.bf16.f32 " \
        "{%0,%1,%2,%3}, {%4,%5,%6,%7}, {%8,%9}, {%0,%1,%2,%3};" \
        : "+f"((c)[0]), "+f"((c)[1]), "+f"((c)[2]), "+f"((c)[3]) \
        : "r"((a)[0]), "r"((a)[1]), "r"((a)[2]), "r"((a)[3]), "r"((b)[0]), "r"((b)[1]))

// ---------------- K1: MLP -> s_fixed, layer1 on tensor cores ---------------
#define T_TPB 128
#define XSTRIDE 272      // bytes per x row (128 bf16 = 256B + 16B pad)
#define DSTRIDE 20       // floats per D row (16 + 4 pad)

__global__ void __launch_bounds__(T_TPB) mlp_kernel(
    const float* __restrict__ x,
    const float* __restrict__ W1, const float* __restrict__ b1,
    const float* __restrict__ W2, const float* __restrict__ b2,
    const float* __restrict__ W3, const float* __restrict__ b3,
    const float* __restrict__ Wc,
    int n)
{
    // pool: phase 1 = x tile bf16 [128 rows x 272B]; phase 2 = D f32 [128 x 20]
    __shared__ __align__(16) char sPool[T_TPB * XSTRIDE];   // 34816 B
    __shared__ __align__(16) char sBT[16 * XSTRIDE];        // W1^T bf16 [16 n][128 k]
    __shared__ float4 sW2[HID * HID / 4], sW3[HID * HID / 4];
    __shared__ float sb1[HID], sb2[HID], sb3[HID], sWc[HID];

    int tid = threadIdx.x;
    int w = tid >> 5;
    int lane = tid & 31;
    int tileBase = blockIdx.x * T_TPB;
    int myNode = min(tileBase + tid, n - 1);

    uint32_t sXb = (uint32_t)__cvta_generic_to_shared(sPool);
    uint32_t sBTb = (uint32_t)__cvta_generic_to_shared(sBT);

    // ---- stage x: coalesced rows -> bf16 smem tile ----
    // iter i, warp w, lane l: row = i*4 + w, float4-col = l (one full row per warp-LDG)
#pragma unroll 8
    for (int i = 0; i < 32; i++) {
        int row = i * 4 + w;
        int gn = min(tileBase + row, n - 1);
        float4 vv = ((const float4*)(x + (size_t)gn * ND))[lane];
        __nv_bfloat162 p0 = __floats2bfloat162_rn(vv.x, vv.y);
        __nv_bfloat162 p1 = __floats2bfloat162_rn(vv.z, vv.w);
        uint2 pk = make_uint2(*(uint32_t*)&p0, *(uint32_t*)&p1);
        *(uint2*)(sPool + row * XSTRIDE + lane * 8) = pk;
    }

    // ---- W1^T bf16: thread tid = k row of W1; scatter 16 bf16 into column k
    {
        const float4* wrow = (const float4*)(W1 + tid * HID);
        float4 wv[4] = {wrow[0], wrow[1], wrow[2], wrow[3]};
        const float* wf = (const float*)wv;
#pragma unroll
        for (int nn = 0; nn < HID; nn++)
            *(__nv_bfloat16*)(sBT + nn * XSTRIDE + tid * 2) = __float2bfloat16(wf[nn]);
    }
    if (tid < HID * HID / 4) {
        sW2[tid] = ((const float4*)W2)[tid];
        sW3[tid] = ((const float4*)W3)[tid];
    }
    if (tid < HID) {
        sb1[tid] = b1[tid]; sb2[tid] = b2[tid]; sb3[tid] = b3[tid]; sWc[tid] = Wc[tid];
    }
    __syncthreads();

    // ---- per-lane ldmatrix base addresses ----
    // A x4 tiles: lanes 0-7 rows+0/k+0, 8-15 rows+8/k+0, 16-23 rows+0/k+8, 24-31 rows+8/k+8
    int rA = (lane & 7) + ((lane >> 3) & 1) * 8;
    uint32_t aOff = (uint32_t)((lane >> 4) & 1) * 16u;
    uint32_t aB0 = sXb + (uint32_t)(32 * w + rA) * XSTRIDE + aOff;        // m-tile 0
    uint32_t aB1 = aB0 + 16u * XSTRIDE;                                    // m-tile 1 (+16 rows)
    // B x2 tiles: lanes 0-7 k+0, 8-15 k+8 (rows = n)
    uint32_t bB0 = sBTb + (uint32_t)(lane & 7) * XSTRIDE + (uint32_t)((lane >> 3) & 1) * 16u;
    uint32_t bB1 = bB0 + 8u * XSTRIDE;                                     // n-tile 1 (+8 n rows)

    float c00[4] = {0, 0, 0, 0}, c01[4] = {0, 0, 0, 0};
    float c10[4] = {0, 0, 0, 0}, c11[4] = {0, 0, 0, 0};

#pragma unroll
    for (int k = 0; k < 8; k++) {
        uint32_t a0[4], a1[4], b0[2], b1v[2];
        uint32_t kb = (uint32_t)k * 32u;  // 16 bf16 = 32 bytes per k-step
        LDSM4(a0, aB0 + kb);
        LDSM4(a1, aB1 + kb);
        LDSM2(b0, bB0 + kb);
        LDSM2(b1v, bB1 + kb);
        MMA16816(c00, a0, b0);
        MMA16816(c01, a0, b1v);
        MMA16816(c10, a1, b0);
        MMA16816(c11, a1, b1v);
    }
    __syncthreads();  // all ldmatrix reads of x done before pool reuse

    // ---- scatter D fragments into pool (f32 [128 x DSTRIDE]) ----
    float* sD = (float*)sPool;
    {
        int g = lane >> 2, tig = lane & 3;
        int col0 = 2 * tig, col1 = 8 + 2 * tig;
        int r0 = 32 * w + g;
        *(float2*)(sD + r0 * DSTRIDE + col0)        = make_float2(c00[0], c00[1]);
        *(float2*)(sD + (r0 + 8) * DSTRIDE + col0)  = make_float2(c00[2], c00[3]);
        *(float2*)(sD + r0 * DSTRIDE + col1)        = make_float2(c01[0], c01[1]);
        *(float2*)(sD + (r0 + 8) * DSTRIDE + col1)  = make_float2(c01[2], c01[3]);
        int r1 = r0 + 16;
        *(float2*)(sD + r1 * DSTRIDE + col0)        = make_float2(c10[0], c10[1]);
        *(float2*)(sD + (r1 + 8) * DSTRIDE + col0)  = make_float2(c10[2], c10[3]);
        *(float2*)(sD + r1 * DSTRIDE + col1)        = make_float2(c11[0], c11[1]);
        *(float2*)(sD + (r1 + 8) * DSTRIDE + col1)  = make_float2(c11[2], c11[3]);
    }
    __syncthreads();

    // ---- bias + tanh, then layers 2/3 in fp32 f32x2 (proven path) ----
    float t0[HID];
#pragma unroll
    for (int j = 0; j < HID; j++)
        t0[j] = ftanh(sD[tid * DSTRIDE + j] + sb1[j]);

    u64 a0v[8];
    const u64* sb2p = (const u64*)sb2;
#pragma unroll
    for (int q = 0; q < 8; q++) a0v[q] = sb2p[q];
#pragma unroll
    for (int i = 0; i < HID; i++) {
        const ulonglong2* wr = (const ulonglong2*)(sW2 + i * 4);
        u64 p0;
        PACK2(p0, t0[i]);
#pragma unroll
        for (int q = 0; q < 4; q++) {
            ulonglong2 ww = wr[q];
            FMA2(a0v[2 * q],     p0, ww.x);
            FMA2(a0v[2 * q + 1], p0, ww.y);
        }
    }
#pragma unroll
    for (int q = 0; q < 8; q++) {
        uint32_t lo = (uint32_t)(a0v[q] & 0xffffffffu), hi = (uint32_t)(a0v[q] >> 32);
        t0[2 * q]     = ftanh(__uint_as_float(lo));
        t0[2 * q + 1] = ftanh(__uint_as_float(hi));
    }

    const u64* sb3p = (const u64*)sb3;
#pragma unroll
    for (int q = 0; q < 8; q++) a0v[q] = sb3p[q];
#pragma unroll
    for (int i = 0; i < HID; i++) {
        const ulonglong2* wr = (const ulonglong2*)(sW3 + i * 4);
        u64 p0;
        PACK2(p0, t0[i]);
#pragma unroll
        for (int q = 0; q < 4; q++) {
            ulonglong2 ww = wr[q];
            FMA2(a0v[2 * q],     p0, ww.x);
            FMA2(a0v[2 * q + 1], p0, ww.y);
        }
    }

    float s0 = 0.f;
#pragma unroll
    for (int q = 0; q < 8; q++) {
        uint32_t lo = (uint32_t)(a0v[q] & 0xffffffffu), hi = (uint32_t)(a0v[q] >> 32);
        s0 += ftanh(__uint_as_float(lo)) * sWc[2 * q];
        s0 += ftanh(__uint_as_float(hi)) * sWc[2 * q + 1];
    }
    // clamped duplicate writes carry identical values -> benign
    g_si[myNode] = (1 << 24) + __float2int_rn(s0 * 65536.0f);
}

// ------ K2: single edge pass: udi[src] += si[dst]  (one RED.ADD.32) -------
#define E_TPB 256
#define E_EPT 8

__global__ void __launch_bounds__(E_TPB) edge_kernel(
    const int* __restrict__ src, const int* __restrict__ dst, int e)
{
    long base = (long)(blockIdx.x * E_TPB + threadIdx.x) * E_EPT;
    if (base + E_EPT <= e) {
        int4 da = *(const int4*)(dst + base);
        int4 db = *(const int4*)(dst + base + 4);
        int4 sa = *(const int4*)(src + base);
        int4 sb = *(const int4*)(src + base + 4);
        int v0 = __ldg(&g_si[da.x]), v1 = __ldg(&g_si[da.y]);
        int v2 = __ldg(&g_si[da.z]), v3 = __ldg(&g_si[da.w]);
        int v4 = __ldg(&g_si[db.x]), v5 = __ldg(&g_si[db.y]);
        int v6 = __ldg(&g_si[db.z]), v7 = __ldg(&g_si[db.w]);
        atomicAdd(&g_udi[sa.x], v0);
        atomicAdd(&g_udi[sa.y], v1);
        atomicAdd(&g_udi[sa.z], v2);
        atomicAdd(&g_udi[sa.w], v3);
        atomicAdd(&g_udi[sb.x], v4);
        atomicAdd(&g_udi[sb.y], v5);
        atomicAdd(&g_udi[sb.z], v6);
        atomicAdd(&g_udi[sb.w], v7);
    } else {
        for (long i = base; i < e; i++)
            atomicAdd(&g_udi[src[i]], __ldg(&g_si[dst[i]]));
    }
}

// ------ K3: node pass: acc = sum_m u[m]/cnt[m]; sigmoid; reset state ------
#define N_TPB 256

__global__ void __launch_bounds__(N_TPB) node_kernel(
    const float* __restrict__ bc, float* __restrict__ out, int n, float inv_n)
{
    __shared__ float sRed[N_TPB / 32];
    int tid = threadIdx.x;
    int i = blockIdx.x * N_TPB + tid;
    float term = 0.f;

    if (i < n) {
        int v = g_udi[i];
        if (v != 0) {
            int cnt = (v + (1 << 23)) >> 24;
            float u = (float)(v - (cnt << 24)) * (1.0f / 65536.0f);
            term = u * __frcp_rn((float)cnt);
            g_udi[i] = 0;  // restore for next graph replay
        }
    }

    unsigned m = 0xffffffffu;
#pragma unroll
    for (int off = 16; off > 0; off >>= 1)
        term += __shfl_down_sync(m, term, off);
    if ((tid & 31) == 0) sRed[tid >> 5] = term;
    __syncthreads();

    if (tid == 0) {
        float v = 0.f;
#pragma unroll
        for (int wq = 0; wq < N_TPB / 32; wq++) v += sRed[wq];
        atomicAdd(&g_acc, v);
        __threadfence();
        unsigned ticket = atomicInc(&g_done, gridDim.x - 1);  // wraps to 0 on last
        if (ticket == gridDim.x - 1) {
            float z = g_acc * inv_n + bc[0];
            out[0] = 1.0f / (1.0f + __expf(-z));
            g_acc = 0.f;  // restore for next replay
        }
    }
}

extern "C" void kernel_launch(void* const* d_in, const int* in_sizes, int n_in,
                              void* d_out, int out_size) {
    const float* x    = (const float*)d_in[0];
    const int*   esrc = (const int*)  d_in[1];
    const int*   edst = (const int*)  d_in[2];
    const float* W1   = (const float*)d_in[3];
    const float* b1   = (const float*)d_in[4];
    const float* W2   = (const float*)d_in[5];
    const float* b2   = (const float*)d_in[6];
    const float* W3   = (const float*)d_in[7];
    const float* b3   = (const float*)d_in[8];
    const float* Wc   = (const float*)d_in[9];
    const float* bc   = (const float*)d_in[10];
    float* out = (float*)d_out;

    int n = in_sizes[0] / ND;
    int e = in_sizes[1];
    if (n > N_MAX) n = N_MAX;

    int nMlp = (n + T_TPB - 1) / T_TPB;
    mlp_kernel<<<nMlp, T_TPB>>>(x, W1, b1, W2, b2, W3, b3, Wc, n);

    int nEdge = (e + E_TPB * E_EPT - 1) / (E_TPB * E_EPT);
    edge_kernel<<<nEdge, E_TPB>>>(esrc, edst, e);

    int nNode = (n + N_TPB - 1) / N_TPB;
    node_kernel<<<nNode, N_TPB>>>(bc, out, n, 1.0f / (float)n);
}